// round 12
// baseline (speedup 1.0000x reference)
#include <cuda_runtime.h>

#define F_DIM 513
#define T_DIM 256
#define C_DIM 8
#define N_DIM 4
#define TSPLIT 7
#define TF (T_DIM * F_DIM)        // 131328
#define NF (N_DIM * F_DIM)        // 2052
#define DIAG_LOAD 7.0710678118654755e-4f  // 0.001/sqrt(2)

// Partial covariances: [input(2)][n(4)][chunk(7)][entry(64)][f(513)]
// entry 0..7 = diag (real), 8..35 = off-diag re (kk order), 36..63 = off-diag im
__device__ float g_partial[2 * N_DIM * TSPLIT * 64 * F_DIM];
// conj(W): [n][c][{re,im}][f]
__device__ float g_wc[N_DIM * C_DIM * 2 * F_DIM];

// chunk boundaries for TSPLIT=7: 4 chunks of 37 t, 3 of 36 t
__device__ __forceinline__ int chunk_start(int y) { return y * 36 + min(y, 4); }

// ---- packed fp32x2 helpers (FFMA2 is PTX-only) ----
__device__ __forceinline__ unsigned long long pack2(float lo, float hi) {
    unsigned long long r;
    asm("mov.b64 %0, {%1, %2};" : "=l"(r) : "f"(lo), "f"(hi));
    return r;
}
__device__ __forceinline__ void fma2(unsigned long long& acc,
                                     unsigned long long a, unsigned long long b) {
    asm("fma.rn.f32x2 %0, %1, %2, %0;" : "+l"(acc) : "l"(a), "l"(b));
}
__device__ __forceinline__ float hsum2(unsigned long long v) {
    float lo, hi;
    asm("mov.b64 {%0, %1}, %2;" : "=f"(lo), "=f"(hi) : "l"(v));
    return lo + hi;
}

// Group predicates (2x2 channel blocking of the 8x8 Hermitian matrix):
// g0: diag 0-3 + pairs within {0..3}        (channels 0-3,   8 loads)
// g1: diag 4-7 + pairs within {4..7}        (channels 4-7,   8 loads)
// g2: pairs i in 0..3, j in {4,5}           (channels 0-5,  12 loads)
// g3: pairs i in 0..3, j in {6,7}           (ch 0-3 + 6,7,  12 loads)
template <int G> __device__ constexpr bool ch_used(int c) {
    return (G == 0) ? (c < 4)
         : (G == 1) ? (c >= 4)
         : (G == 2) ? (c < 6)
         :            (c < 4 || c >= 6);
}
template <int G> __device__ constexpr bool pair_in(int i, int j) {
    return (G == 0) ? (j < 4)
         : (G == 1) ? (i >= 4)
         : (G == 2) ? (i < 4 && j >= 4 && j < 6)
         :            (i < 4 && j >= 6);
}
template <int G> __device__ constexpr bool diag_in(int c) {
    return (G == 0) ? (c < 4) : (G == 1) ? (c >= 4) : false;
}

// -------------------------------------------------------------------------
// Pass 1: channel-blocked partial covariance.
// Block (128 f, 4 groups) = 512 thr, <=63 regs -> 2 blocks/SM, 32 warps/SM.
// grid (5, 7, 8) = 280 blocks = single wave.
// Per pair k: accA += P[i]*P[j] (lanes xr_i*xr_j, xi_i*xi_j),
//             accB += Q[i]*P[j] (lanes xi_i*xr_j, -xr_i*xi_j),
// horizontal-summed at the epilogue (re = A.lo+A.hi, im = B.lo+B.hi).
// -------------------------------------------------------------------------
template <int G>
__device__ __forceinline__ void cov_group(
    const float* __restrict__ base, int t0, int t1,
    float* __restrict__ dst, bool valid)
{
    unsigned long long accA[8], accB[8], dd[4];
#pragma unroll
    for (int a = 0; a < 8; a++) { accA[a] = 0ull; accB[a] = 0ull; }
#pragma unroll
    for (int a = 0; a < 4; a++) dd[a] = 0ull;

    for (int t = t0; t < t1; ++t) {
        const float* p = base + (size_t)t * F_DIM;
        float xr[8], xi[8];
#pragma unroll
        for (int c = 0; c < 8; c++) {
            if (ch_used<G>(c)) {
                xr[c] = __ldg(p + (size_t)c * TF);
                xi[c] = __ldg(p + (size_t)(8 + c) * TF);
            }
        }
        unsigned long long P[8], Q[8];
#pragma unroll
        for (int c = 0; c < 8; c++) {
            if (ch_used<G>(c)) {
                P[c] = pack2(xr[c], xi[c]);
                Q[c] = pack2(xi[c], -xr[c]);
            }
        }
#pragma unroll
        for (int c = 0; c < 8; c++)
            if (diag_in<G>(c)) fma2(dd[c & 3], P[c], P[c]);
        int k = 0;
#pragma unroll
        for (int i = 0; i < 8; i++)
#pragma unroll
            for (int j = i + 1; j < 8; j++) {
                if (pair_in<G>(i, j)) {
                    fma2(accA[k], P[i], P[j]);
                    fma2(accB[k], Q[i], P[j]);
                    k++;
                }
            }
    }

    if (!valid) return;
    // store: diag then pairs (kk = 7i - i(i-1)/2 + (j-i-1))
#pragma unroll
    for (int c = 0; c < 8; c++)
        if (diag_in<G>(c)) dst[(size_t)c * F_DIM] = hsum2(dd[c & 3]);
    int k = 0;
#pragma unroll
    for (int i = 0; i < 8; i++)
#pragma unroll
        for (int j = i + 1; j < 8; j++) {
            if (pair_in<G>(i, j)) {
                int kk = 7 * i - (i * (i - 1)) / 2 + (j - i - 1);
                dst[(size_t)(8 + kk) * F_DIM]  = hsum2(accA[k]);
                dst[(size_t)(36 + kk) * F_DIM] = hsum2(accB[k]);
                k++;
            }
        }
}

__global__ __launch_bounds__(512, 2) void cov_partial_kernel(
    const float* __restrict__ target, const float* __restrict__ noise)
{
    int fl = threadIdx.x;               // 0..127
    int g  = threadIdx.y;               // 0..3
    int gf = blockIdx.x * 128 + fl;
    int fc = min(gf, F_DIM - 1);
    int inp = blockIdx.z & 1;
    int n   = blockIdx.z >> 1;
    const float* src = inp ? noise : target;
    int t0 = chunk_start(blockIdx.y);
    int t1 = chunk_start(blockIdx.y + 1);

    const float* base = src + (size_t)(16 * n) * TF + fc;
    float* dst = g_partial +
        (size_t)((inp * N_DIM + n) * TSPLIT + blockIdx.y) * 64 * F_DIM + gf;
    bool valid = (gf < F_DIM);

    switch (g) {
        case 0: cov_group<0>(base, t0, t1, dst, valid); break;
        case 1: cov_group<1>(base, t0, t1, dst, valid); break;
        case 2: cov_group<2>(base, t0, t1, dst, valid); break;
        default: cov_group<3>(base, t0, t1, dst, valid); break;
    }
}

// -------------------------------------------------------------------------
// Pass 2: per-(n,f) solve. Block = 256 thr = 8 matrices -> 257 blocks.
// Stage: reduce 7 chunks per entry, coalesced. Solve: threads 0..63.
// -------------------------------------------------------------------------
__global__ __launch_bounds__(256) void solve_kernel(const int* __restrict__ ref_idx)
{
    __shared__ float s_cov[2][64][9];    // [input][entry][matrix + pad]
    int tid = threadIdx.x;
    int m0  = blockIdx.x * 8;
    const float invT = 1.0f / (float)T_DIM;

#pragma unroll
    for (int r = 0; r < 4; r++) {
        int o  = r * 256 + tid;
        int mi = o & 7;
        int e  = (o >> 3) & 63;
        int ip = o >> 9;
        int m  = min(m0 + mi, NF - 1);
        int n  = m / F_DIM, f = m % F_DIM;
        const float* base = g_partial +
            (size_t)((ip * N_DIM + n) * TSPLIT) * 64 * F_DIM +
            (size_t)e * F_DIM + f;
        float sv = 0.f;
#pragma unroll
        for (int ch = 0; ch < TSPLIT; ch++)
            sv += base[(size_t)ch * 64 * F_DIM];
        s_cov[ip][e][mi] = sv * invT;
    }
    __syncthreads();

    if (tid >= 64) return;
    int mi = tid >> 3;
    int i  = tid & 7;
    int m  = min(m0 + mi, NF - 1);
    int n  = m / F_DIM, f = m % F_DIM;
    const unsigned FULL = 0xffffffffu;

    float nr[8], ni[8];
#pragma unroll
    for (int j = 0; j < 8; j++) {
        if (j == i) { nr[j] = s_cov[1][i][mi] + DIAG_LOAD; ni[j] = DIAG_LOAD; }
        else {
            int a = min(i, j), b = max(i, j);
            int kk = 7 * a - (a * (a - 1)) / 2 + (b - a - 1);
            float sign = (i < j) ? 1.f : -1.f;
            nr[j] = s_cov[1][8 + kk][mi];
            ni[j] = sign * s_cov[1][36 + kk][mi];
        }
    }

#pragma unroll
    for (int kp = 0; kp < 8; kp++) {
        float akk_r = __shfl_sync(FULL, nr[kp], kp, 8);
        float akk_i = __shfl_sync(FULL, ni[kp], kp, 8);
        float idn = 1.0f / fmaf(akk_r, akk_r, akk_i * akk_i);
        float p_r = akk_r * idn, p_i = -akk_i * idn;
        float s_r[8], s_i[8];
#pragma unroll
        for (int j = 0; j < 8; j++) {
            float ar = __shfl_sync(FULL, nr[j], kp, 8);
            float ai = __shfl_sync(FULL, ni[j], kp, 8);
            s_r[j] = ar * p_r - ai * p_i;
            s_i[j] = ar * p_i + ai * p_r;
        }
        if (i == kp) {
#pragma unroll
            for (int j = 0; j < 8; j++) { nr[j] = s_r[j]; ni[j] = s_i[j]; }
            nr[kp] = p_r; ni[kp] = p_i;
        } else {
            float f_r = nr[kp], f_i = ni[kp];
#pragma unroll
            for (int j = 0; j < 8; j++) {
                if (j == kp) continue;
                nr[j] -= f_r * s_r[j] - f_i * s_i[j];
                ni[j] -= f_r * s_i[j] + f_i * s_r[j];
            }
            nr[kp] = -(f_r * p_r - f_i * p_i);
            ni[kp] = -(f_r * p_i + f_i * p_r);
        }
    }

    float tr_[8], ti[8];
#pragma unroll
    for (int j = 0; j < 8; j++) {
        if (j == i) { tr_[j] = s_cov[0][i][mi]; ti[j] = 0.f; }
        else {
            int a = min(i, j), b = max(i, j);
            int kk = 7 * a - (a * (a - 1)) / 2 + (b - a - 1);
            float sign = (i < j) ? 1.f : -1.f;
            tr_[j] = s_cov[0][8 + kk][mi];
            ti[j]  = sign * s_cov[0][36 + kk][mi];
        }
    }

    float trc_r = 0.f, trc_i = 0.f;
#pragma unroll
    for (int j = 0; j < 8; j++) {
        trc_r += nr[j] * tr_[j] + ni[j] * ti[j];
        trc_i += ni[j] * tr_[j] - nr[j] * ti[j];
    }
#pragma unroll
    for (int off = 4; off > 0; off >>= 1) {
        trc_r += __shfl_xor_sync(FULL, trc_r, off, 8);
        trc_i += __shfl_xor_sync(FULL, trc_i, off, 8);
    }

    int ref = *ref_idx;
    float pr = 0.f, pi = 0.f;
#pragma unroll
    for (int jj = 0; jj < 8; jj++)
        if (jj == ref) { pr = tr_[jj]; pi = ti[jj]; }

    float w_r = 0.f, w_i = 0.f;
#pragma unroll
    for (int j = 0; j < 8; j++) {
        float br = __shfl_sync(FULL, pr, j, 8);
        float bi = __shfl_sync(FULL, pi, j, 8);
        w_r += nr[j] * br - ni[j] * bi;
        w_i += nr[j] * bi + ni[j] * br;
    }

    float ldn = 1.0f / fmaf(trc_r, trc_r, trc_i * trc_i);
    float lr = trc_r * ldn, li = -trc_i * ldn;
    float Wr = w_r * lr - w_i * li;
    float Wi = w_r * li + w_i * lr;

    g_wc[((n * 8 + i) * 2 + 0) * F_DIM + f] = Wr;
    g_wc[((n * 8 + i) * 2 + 1) * F_DIM + f] = -Wi;
}

// -------------------------------------------------------------------------
// Pass 3: beamform, TPER=2 (best measured), loads hoisted.
// grid (5, 128, 4) = 2560 blocks of 128.
// -------------------------------------------------------------------------
#define TPER 2
__global__ __launch_bounds__(128) void beamform_kernel(
    const float* __restrict__ mix, float* __restrict__ out)
{
    int f = blockIdx.x * blockDim.x + threadIdx.x;
    if (f >= F_DIM) return;
    int n  = blockIdx.z;
    int t0 = blockIdx.y * TPER;

    float wr[8], wi[8];
#pragma unroll
    for (int c = 0; c < 8; c++) {
        wr[c] = g_wc[((n * 8 + c) * 2 + 0) * F_DIM + f];
        wi[c] = g_wc[((n * 8 + c) * 2 + 1) * F_DIM + f];
    }

    const float* baseR = mix + (size_t)(16 * n) * TF + f;
    const float* baseI = mix + (size_t)(16 * n + 8) * TF + f;
    float* outR = out + (size_t)(2 * n) * TF + f;      // (N,2,1,T,F)
    float* outI = out + (size_t)(2 * n + 1) * TF + f;

    float yr[TPER][8], yi[TPER][8];
#pragma unroll
    for (int dt = 0; dt < TPER; dt++) {
        int off = (t0 + dt) * F_DIM;
#pragma unroll
        for (int c = 0; c < 8; c++) {
            yr[dt][c] = __ldg(baseR + (size_t)c * TF + off);
            yi[dt][c] = __ldg(baseI + (size_t)c * TF + off);
        }
    }
#pragma unroll
    for (int dt = 0; dt < TPER; dt++) {
        float Xr = 0.f, Xi = 0.f;
#pragma unroll
        for (int c = 0; c < 8; c++) {
            Xr += wr[c] * yr[dt][c] - wi[c] * yi[dt][c];
            Xi += wr[c] * yi[dt][c] + wi[c] * yr[dt][c];
        }
        int off = (t0 + dt) * F_DIM;
        outR[off] = Xr;
        outI[off] = Xi;
    }
}

// -------------------------------------------------------------------------
extern "C" void kernel_launch(void* const* d_in, const int* in_sizes, int n_in,
                              void* d_out, int out_size)
{
    const float* mixture = (const float*)d_in[0];
    const float* target  = (const float*)d_in[1];
    const float* noise   = (const float*)d_in[2];
    const int*   ref     = (const int*)d_in[3];
    float* out = (float*)d_out;

    dim3 b1(128, 4);
    dim3 g1((F_DIM + 127) / 128, TSPLIT, N_DIM * 2);   // 5 x 7 x 8 = 280 blocks
    cov_partial_kernel<<<g1, b1>>>(target, noise);

    int groups = (NF + 7) / 8;                          // 257 blocks
    solve_kernel<<<groups, 256>>>(ref);

    dim3 g3((F_DIM + 127) / 128, T_DIM / TPER, N_DIM);
    beamform_kernel<<<g3, 128>>>(mixture, out);
}

// round 13
// speedup vs baseline: 1.5682x; 1.5682x over previous
#include <cuda_runtime.h>

#define F_DIM 513
#define T_DIM 256
#define C_DIM 8
#define N_DIM 4
#define TF (T_DIM * F_DIM)        // 131328
#define NF (N_DIM * F_DIM)        // 2052
#define DIAG_LOAD 7.0710678118654755e-4f  // 0.001/sqrt(2)

#define GRID 136                   // 17 f-blocks x 8 (inp,n); <= 148 SMs => co-resident
#define NTHR 512
#define MIX_F4 2101248u            // mixture floats / 4 = 8404992/4

// FINAL covariances (already /T): [input(2)][n(4)][entry(64)][f(513)]
__device__ float g_cov[2 * N_DIM * 64 * F_DIM];
// conj(W): [n][c][{re,im}][f]
__device__ float g_wc[N_DIM * C_DIM * 2 * F_DIM];
// grid barrier counter (monotonic across graph replays; each launch adds 2*GRID)
__device__ unsigned int g_bar;

// ---- packed fp32x2 helpers (FFMA2 is PTX-only) ----
__device__ __forceinline__ unsigned long long pack2(float lo, float hi) {
    unsigned long long r;
    asm("mov.b64 %0, {%1, %2};" : "=l"(r) : "f"(lo), "f"(hi));
    return r;
}
__device__ __forceinline__ void fma2(unsigned long long& acc,
                                     unsigned long long a, unsigned long long b) {
    asm("fma.rn.f32x2 %0, %1, %2, %0;" : "+l"(acc) : "l"(a), "l"(b));
}
__device__ __forceinline__ void unpack2(unsigned long long v, float& lo, float& hi) {
    asm("mov.b64 {%0, %1}, %2;" : "=f"(lo), "=f"(hi) : "l"(v));
}

__device__ __forceinline__ void grid_barrier() {
    __syncthreads();
    if (threadIdx.x == 0) {
        __threadfence();
        unsigned old = atomicAdd(&g_bar, 1u);
        unsigned target = (old / GRID + 1u) * GRID;
        while (*(volatile unsigned int*)&g_bar < target) __nanosleep(64);
        __threadfence();
    }
    __syncthreads();
}

// -------------------------------------------------------------------------
// One persistent kernel, 136 blocks x 512 threads.
// Phase 1: fused covariance (R11 f32x2 body) + mixture L2-prefetch.
// Phase 2: per-(n,f) 8x8 complex Gauss-Jordan solve (16 matrices/block).
// Phase 3: beamform, mixture served from L2.
// -------------------------------------------------------------------------
__global__ __launch_bounds__(NTHR, 1) void mvdr_kernel(
    const float* __restrict__ mix,
    const float* __restrict__ target,
    const float* __restrict__ noise,
    const int* __restrict__ ref_idx,
    float* __restrict__ out)
{
    __shared__ float s_raw[16 * 16 * 32];   // 32 KB, reused across phases
    int tid = threadIdx.x;
    int bx  = blockIdx.x;

    // ===================== Phase 1: covariance + prefetch =====================
    {
        int fb = bx % 17;
        int z  = bx / 17;
        int fx = tid & 31;
        int sl = tid >> 5;
        int gf = fb * 32 + fx;
        int fc = min(gf, F_DIM - 1);
        int inp = z & 1;
        int n   = z >> 1;
        const float* src = inp ? noise : target;
        int t0 = sl * 16;

        unsigned long long acc[28], dd[8];
#pragma unroll
        for (int k = 0; k < 28; k++) acc[k] = 0ull;
#pragma unroll
        for (int c = 0; c < 8; c++) dd[c] = 0ull;

        const float* base = src + (size_t)(16 * n) * TF + fc + (size_t)t0 * F_DIM;
        const float4* mix4 = (const float4*)mix;
        unsigned pg = (unsigned)(bx * NTHR + tid);
        float pf = 0.f;

#pragma unroll
        for (int tt = 0; tt < 16; ++tt) {
            // prefetch 2 independent float4 of mixture into L2 (.cg)
#pragma unroll
            for (int pk = 0; pk < 2; pk++) {
                unsigned pidx = pg + (unsigned)(tt * 2 + pk) * (GRID * NTHR);
                if (pidx < MIX_F4) {
                    float4 v = __ldcg(mix4 + pidx);
                    pf += v.x + v.y + v.z + v.w;
                }
            }
            const float* p = base + (size_t)tt * F_DIM;
            float x[16];
#pragma unroll
            for (int v = 0; v < 16; v++)
                x[v] = __ldg(p + (size_t)v * TF);

            unsigned long long P[8], Q[8];
#pragma unroll
            for (int c = 0; c < 8; c++) {
                P[c] = pack2(x[c], x[8 + c]);
                Q[c] = pack2(x[8 + c], -x[c]);
                fma2(dd[c], P[c], P[c]);
            }
#pragma unroll
            for (int j = 1; j < 8; j++) {
                unsigned long long BR = pack2(x[j], x[j]);
                unsigned long long BI = pack2(x[8 + j], x[8 + j]);
#pragma unroll
                for (int i = 0; i < j; i++) {
                    int kk = 7 * i - (i * (i - 1)) / 2 + (j - i - 1);
                    fma2(acc[kk], P[i], BR);
                    fma2(acc[kk], Q[i], BI);
                }
            }
        }
        asm volatile("" :: "f"(pf));   // keep prefetch loads alive

        float d[8], orr[28], oii[28];
#pragma unroll
        for (int c = 0; c < 8; c++) {
            float a, b; unpack2(dd[c], a, b); d[c] = a + b;
        }
#pragma unroll
        for (int k = 0; k < 28; k++) unpack2(acc[k], orr[k], oii[k]);

        // cross-slice reduction, 4 batches of 16 entries
        float (*sred)[16][32] = (float(*)[16][32])s_raw;
        float* gout = g_cov + (size_t)(inp * N_DIM + n) * 64 * F_DIM;
        const float invT = 1.0f / (float)T_DIM;

#pragma unroll
        for (int b = 0; b < 4; b++) {
#pragma unroll
            for (int q = 0; q < 16; q++) {
                int e = b * 16 + q;
                float v = (e < 8) ? d[e] : (e < 36 ? orr[e - 8] : oii[e - 36]);
                sred[q][sl][fx] = v;
            }
            __syncthreads();
            {
                float sv = 0.f;
#pragma unroll
                for (int s = 0; s < 16; s++) sv += sred[sl][s][fx];
                if (gf < F_DIM)
                    gout[(size_t)(b * 16 + sl) * F_DIM + gf] = sv * invT;
            }
            __syncthreads();
        }
    }

    grid_barrier();

    // ===================== Phase 2: solve (16 matrices / block) ==============
    {
        int m0 = bx * 16;
        if (m0 < NF) {
            float (*s_cov)[64][17] = (float(*)[64][17])s_raw;  // [2][64][17]
            // cooperative staging: 2*64*16 = 2048 values, 4 per thread
#pragma unroll
            for (int r = 0; r < 4; r++) {
                int o  = r * NTHR + tid;
                int mi = o & 15;
                int e  = (o >> 4) & 63;
                int ip = o >> 10;
                int m  = min(m0 + mi, NF - 1);
                int n  = m / F_DIM, f = m % F_DIM;
                s_cov[ip][e][mi] =
                    g_cov[((size_t)(ip * N_DIM + n) * 64 + e) * F_DIM + f];
            }
            __syncthreads();

            if (tid < 128) {
                int mi = tid >> 3;
                int i  = tid & 7;
                int m  = min(m0 + mi, NF - 1);
                int n  = m / F_DIM, f = m % F_DIM;
                const unsigned FULL = 0xffffffffu;

                float nr[8], ni[8];
#pragma unroll
                for (int j = 0; j < 8; j++) {
                    if (j == i) { nr[j] = s_cov[1][i][mi] + DIAG_LOAD; ni[j] = DIAG_LOAD; }
                    else {
                        int a = min(i, j), b = max(i, j);
                        int kk = 7 * a - (a * (a - 1)) / 2 + (b - a - 1);
                        float sign = (i < j) ? 1.f : -1.f;
                        nr[j] = s_cov[1][8 + kk][mi];
                        ni[j] = sign * s_cov[1][36 + kk][mi];
                    }
                }

#pragma unroll
                for (int kp = 0; kp < 8; kp++) {
                    float akk_r = __shfl_sync(FULL, nr[kp], kp, 8);
                    float akk_i = __shfl_sync(FULL, ni[kp], kp, 8);
                    float idn = 1.0f / fmaf(akk_r, akk_r, akk_i * akk_i);
                    float p_r = akk_r * idn, p_i = -akk_i * idn;
                    float s_r[8], s_i[8];
#pragma unroll
                    for (int j = 0; j < 8; j++) {
                        float ar = __shfl_sync(FULL, nr[j], kp, 8);
                        float ai = __shfl_sync(FULL, ni[j], kp, 8);
                        s_r[j] = ar * p_r - ai * p_i;
                        s_i[j] = ar * p_i + ai * p_r;
                    }
                    if (i == kp) {
#pragma unroll
                        for (int j = 0; j < 8; j++) { nr[j] = s_r[j]; ni[j] = s_i[j]; }
                        nr[kp] = p_r; ni[kp] = p_i;
                    } else {
                        float f_r = nr[kp], f_i = ni[kp];
#pragma unroll
                        for (int j = 0; j < 8; j++) {
                            if (j == kp) continue;
                            nr[j] -= f_r * s_r[j] - f_i * s_i[j];
                            ni[j] -= f_r * s_i[j] + f_i * s_r[j];
                        }
                        nr[kp] = -(f_r * p_r - f_i * p_i);
                        ni[kp] = -(f_r * p_i + f_i * p_r);
                    }
                }

                float tr_[8], ti[8];
#pragma unroll
                for (int j = 0; j < 8; j++) {
                    if (j == i) { tr_[j] = s_cov[0][i][mi]; ti[j] = 0.f; }
                    else {
                        int a = min(i, j), b = max(i, j);
                        int kk = 7 * a - (a * (a - 1)) / 2 + (b - a - 1);
                        float sign = (i < j) ? 1.f : -1.f;
                        tr_[j] = s_cov[0][8 + kk][mi];
                        ti[j]  = sign * s_cov[0][36 + kk][mi];
                    }
                }

                float trc_r = 0.f, trc_i = 0.f;
#pragma unroll
                for (int j = 0; j < 8; j++) {
                    trc_r += nr[j] * tr_[j] + ni[j] * ti[j];
                    trc_i += ni[j] * tr_[j] - nr[j] * ti[j];
                }
#pragma unroll
                for (int off = 4; off > 0; off >>= 1) {
                    trc_r += __shfl_xor_sync(FULL, trc_r, off, 8);
                    trc_i += __shfl_xor_sync(FULL, trc_i, off, 8);
                }

                int ref = *ref_idx;
                float pr = 0.f, pi = 0.f;
#pragma unroll
                for (int jj = 0; jj < 8; jj++)
                    if (jj == ref) { pr = tr_[jj]; pi = ti[jj]; }

                float w_r = 0.f, w_i = 0.f;
#pragma unroll
                for (int j = 0; j < 8; j++) {
                    float br = __shfl_sync(FULL, pr, j, 8);
                    float bi = __shfl_sync(FULL, pi, j, 8);
                    w_r += nr[j] * br - ni[j] * bi;
                    w_i += nr[j] * bi + ni[j] * br;
                }

                float ldn = 1.0f / fmaf(trc_r, trc_r, trc_i * trc_i);
                float lr = trc_r * ldn, li = -trc_i * ldn;
                float Wr = w_r * lr - w_i * li;
                float Wi = w_r * li + w_i * lr;

                g_wc[((n * 8 + i) * 2 + 0) * F_DIM + f] = Wr;
                g_wc[((n * 8 + i) * 2 + 1) * F_DIM + f] = -Wi;
            }
        }
    }

    grid_barrier();

    // ===================== Phase 3: beamform (mixture from L2) ===============
    {
        const int TOTAL = N_DIM * T_DIM * F_DIM;   // 525312
        for (int o = bx * NTHR + tid; o < TOTAL; o += GRID * NTHR) {
            int n   = o / (T_DIM * F_DIM);
            int rem = o - n * (T_DIM * F_DIM);
            int t   = rem / F_DIM;
            int f   = rem - t * F_DIM;

            const float* bR = mix + (size_t)(16 * n) * TF + (size_t)t * F_DIM + f;
            const float* bI = bR + (size_t)8 * TF;
            float Xr = 0.f, Xi = 0.f;
#pragma unroll
            for (int c = 0; c < 8; c++) {
                float wr = g_wc[((n * 8 + c) * 2 + 0) * F_DIM + f];
                float wi = g_wc[((n * 8 + c) * 2 + 1) * F_DIM + f];
                float yr = __ldg(bR + (size_t)c * TF);
                float yi = __ldg(bI + (size_t)c * TF);
                Xr += wr * yr - wi * yi;
                Xi += wr * yi + wi * yr;
            }
            out[(size_t)(2 * n) * TF + (size_t)t * F_DIM + f]     = Xr;
            out[(size_t)(2 * n + 1) * TF + (size_t)t * F_DIM + f] = Xi;
        }
    }
}

// -------------------------------------------------------------------------
extern "C" void kernel_launch(void* const* d_in, const int* in_sizes, int n_in,
                              void* d_out, int out_size)
{
    const float* mixture = (const float*)d_in[0];
    const float* target  = (const float*)d_in[1];
    const float* noise   = (const float*)d_in[2];
    const int*   ref     = (const int*)d_in[3];
    float* out = (float*)d_out;

    mvdr_kernel<<<GRID, NTHR>>>(mixture, target, noise, ref, out);
}